// round 2
// baseline (speedup 1.0000x reference)
#include <cuda_runtime.h>
#include <cstdint>

// Problem constants: N=50000, E=600000, IN_DIM=128, HID=256, OUT=128
#define MAXN 50000
#define MAXE 600000
#define DIM 128

// Scratch (device globals — no allocation allowed)
__device__ float g_msg[MAXN * DIM];   // neighbor means [N,128]
__device__ int   g_deg[MAXN];
__device__ int   g_off[MAXN];         // CSR row offsets (exclusive)
__device__ int   g_cur[MAXN];         // fill cursors
__device__ int   g_csr[MAXE];         // src index per CSR slot
__device__ float g_W[256 * 128];      // fused W1@W2
__device__ float g_b[128];            // fused b1@W2 + b2

// ---------------------------------------------------------------------------
// Kernel 1: fuse the two linear layers (no inner activation => collapse)
// ---------------------------------------------------------------------------
__global__ void fuse_weights(const float* __restrict__ W1, const float* __restrict__ b1,
                             const float* __restrict__ W2, const float* __restrict__ b2) {
    int row = blockIdx.x;
    int j = threadIdx.x;            // 0..127
    if (row < 256) {
        float acc = 0.f;
        #pragma unroll 4
        for (int k = 0; k < 256; k++)
            acc += W1[row * 256 + k] * W2[k * 128 + j];
        g_W[row * 128 + j] = acc;
    } else {
        float acc = b2[j];
        #pragma unroll 4
        for (int k = 0; k < 256; k++)
            acc += b1[k] * W2[k * 128 + j];
        g_b[j] = acc;
    }
}

// ---------------------------------------------------------------------------
// Kernel 2: zero degree counters (only 50K ints — msg no longer needs zeroing)
// ---------------------------------------------------------------------------
__global__ void zero_deg(int n) {
    int i = blockIdx.x * blockDim.x + threadIdx.x;
    if (i < n) g_deg[i] = 0;
}

// ---------------------------------------------------------------------------
// Kernel 3: degree histogram (int atomics on 50K L2-resident counters)
// ---------------------------------------------------------------------------
__global__ void histogram(const int* __restrict__ dst, int E) {
    int e = blockIdx.x * blockDim.x + threadIdx.x;
    if (e < E) atomicAdd(&g_deg[dst[e]], 1);
}

// ---------------------------------------------------------------------------
// Kernel 4: single-block exclusive prefix scan over degrees -> offsets+cursors
// 1024 threads, each owns a contiguous chunk of ceil(n/1024) nodes.
// ---------------------------------------------------------------------------
__global__ __launch_bounds__(1024) void scan_offsets(int n) {
    __shared__ int sums[1024];
    int t = threadIdx.x;
    int chunk = (n + 1023) / 1024;
    int start = t * chunk;
    int end = min(start + chunk, n);
    int s = 0;
    for (int i = start; i < end; i++) s += g_deg[i];
    sums[t] = s;
    __syncthreads();
    // Hillis-Steele inclusive scan
    #pragma unroll
    for (int ofs = 1; ofs < 1024; ofs <<= 1) {
        int v = (t >= ofs) ? sums[t - ofs] : 0;
        __syncthreads();
        sums[t] += v;
        __syncthreads();
    }
    int run = (t == 0) ? 0 : sums[t - 1];   // exclusive offset for this chunk
    for (int i = start; i < end; i++) {
        g_off[i] = run;
        g_cur[i] = run;
        run += g_deg[i];
    }
}

// ---------------------------------------------------------------------------
// Kernel 5: bucket-fill CSR (int atomics for slot assignment)
// ---------------------------------------------------------------------------
__global__ void fill_csr(const int* __restrict__ src, const int* __restrict__ dst, int E) {
    int e = blockIdx.x * blockDim.x + threadIdx.x;
    if (e >= E) return;
    int p = atomicAdd(&g_cur[dst[e]], 1);
    g_csr[p] = src[e];
}

// ---------------------------------------------------------------------------
// Kernel 6: gather + mean. One warp per node, lane l owns floats [4l,4l+4).
// Register accumulation; no f32 atomics anywhere.
// ---------------------------------------------------------------------------
__global__ void gather_csr(const float* __restrict__ h, int n) {
    int warp = (blockIdx.x * blockDim.x + threadIdx.x) >> 5;
    int lane = threadIdx.x & 31;
    if (warp >= n) return;
    int beg = g_off[warp];
    int deg = g_deg[warp];
    float4 acc = make_float4(0.f, 0.f, 0.f, 0.f);

    for (int i = 0; i < deg; i += 32) {
        // stage up to 32 neighbor indices across the warp, broadcast via shfl
        int idx = (i + lane < deg) ? g_csr[beg + i + lane] : 0;
        int m = min(32, deg - i);
        #pragma unroll 4
        for (int j = 0; j < m; j++) {
            int s = __shfl_sync(0xffffffff, idx, j);
            float4 v = reinterpret_cast<const float4*>(h)[(size_t)s * (DIM / 4) + lane];
            acc.x += v.x; acc.y += v.y; acc.z += v.z; acc.w += v.w;
        }
    }
    float inv = 1.0f / fmaxf((float)deg, 1.0f);
    acc.x *= inv; acc.y *= inv; acc.z *= inv; acc.w *= inv;
    reinterpret_cast<float4*>(g_msg)[(size_t)warp * (DIM / 4) + lane] = acc;
}

// ---------------------------------------------------------------------------
// Kernel 7: fused GEMM + bias + relu.
//   out[n,:] = relu( [h[n,:], msg[n,:]] @ W + b )   (M=N, K=256, N=128)
// 128x128 block tile, BK=16, 8x8 per-thread, packed fma.rn.f32x2.
// ---------------------------------------------------------------------------
#define BM 128
#define BN 128
#define BK 16
#define TM 8
#define TN 8

__global__ __launch_bounds__(256) void fused_gemm(const float* __restrict__ h,
                                                  float* __restrict__ out, int M) {
    __shared__ float As[BK][BM];   // transposed: As[k][m]
    __shared__ float Bs[BK][BN];

    int tid = threadIdx.x;
    int tx = tid & 15;     // N direction (16)
    int ty = tid >> 4;     // M direction (16)
    int row0 = blockIdx.x * BM;

    unsigned long long acc[TM][TN / 2];
    #pragma unroll
    for (int m = 0; m < TM; m++)
        #pragma unroll
        for (int j = 0; j < TN / 2; j++) acc[m][j] = 0ULL;

    for (int k0 = 0; k0 < 256; k0 += BK) {
        const float* Abase = (k0 < 128) ? (h + k0) : (g_msg + (k0 - 128));
        #pragma unroll
        for (int l = 0; l < 2; l++) {
            int idx = tid + l * 256;
            int r = idx >> 2;
            int c = (idx & 3) * 4;
            float4 v = make_float4(0.f, 0.f, 0.f, 0.f);
            int gr = row0 + r;
            if (gr < M)
                v = *reinterpret_cast<const float4*>(Abase + (size_t)gr * DIM + c);
            As[c + 0][r] = v.x; As[c + 1][r] = v.y;
            As[c + 2][r] = v.z; As[c + 3][r] = v.w;
        }
        #pragma unroll
        for (int l = 0; l < 2; l++) {
            int idx = tid + l * 256;
            int r = idx >> 5;
            int c = (idx & 31) * 4;
            *reinterpret_cast<float4*>(&Bs[r][c]) =
                *reinterpret_cast<const float4*>(g_W + (size_t)(k0 + r) * 128 + c);
        }
        __syncthreads();

        #pragma unroll
        for (int kk = 0; kk < BK; kk++) {
            float a[TM];
            #pragma unroll
            for (int m = 0; m < TM; m += 4) {
                float4 t = *reinterpret_cast<const float4*>(&As[kk][ty * TM + m]);
                a[m] = t.x; a[m + 1] = t.y; a[m + 2] = t.z; a[m + 3] = t.w;
            }
            unsigned long long b2v[4];
            const unsigned long long* bp =
                reinterpret_cast<const unsigned long long*>(&Bs[kk][tx * TN]);
            b2v[0] = bp[0]; b2v[1] = bp[1]; b2v[2] = bp[2]; b2v[3] = bp[3];
            #pragma unroll
            for (int m = 0; m < TM; m++) {
                unsigned long long aa;
                asm("mov.b64 %0, {%1, %1};" : "=l"(aa) : "f"(a[m]));
                #pragma unroll
                for (int j = 0; j < 4; j++)
                    asm("fma.rn.f32x2 %0, %1, %2, %0;"
                        : "+l"(acc[m][j]) : "l"(aa), "l"(b2v[j]));
            }
        }
        __syncthreads();
    }

    float bias[TN];
    #pragma unroll
    for (int j = 0; j < TN; j++) bias[j] = g_b[tx * TN + j];

    #pragma unroll
    for (int m = 0; m < TM; m++) {
        int gr = row0 + ty * TM + m;
        if (gr >= M) continue;
        float res[TN];
        #pragma unroll
        for (int j = 0; j < 4; j++) {
            float lo, hi;
            asm("mov.b64 {%0, %1}, %2;" : "=f"(lo), "=f"(hi) : "l"(acc[m][j]));
            res[2 * j] = lo; res[2 * j + 1] = hi;
        }
        float4 o0, o1;
        o0.x = fmaxf(res[0] + bias[0], 0.f);
        o0.y = fmaxf(res[1] + bias[1], 0.f);
        o0.z = fmaxf(res[2] + bias[2], 0.f);
        o0.w = fmaxf(res[3] + bias[3], 0.f);
        o1.x = fmaxf(res[4] + bias[4], 0.f);
        o1.y = fmaxf(res[5] + bias[5], 0.f);
        o1.z = fmaxf(res[6] + bias[6], 0.f);
        o1.w = fmaxf(res[7] + bias[7], 0.f);
        float* op = out + (size_t)gr * DIM + tx * TN;
        *reinterpret_cast<float4*>(op) = o0;
        *reinterpret_cast<float4*>(op + 4) = o1;
    }
}

// ---------------------------------------------------------------------------
extern "C" void kernel_launch(void* const* d_in, const int* in_sizes, int n_in,
                              void* d_out, int out_size) {
    const float* h  = (const float*)d_in[0];
    const int* src  = (const int*)d_in[1];
    const int* dst  = (const int*)d_in[2];
    const float* W1 = (const float*)d_in[3];
    const float* b1 = (const float*)d_in[4];
    const float* W2 = (const float*)d_in[5];
    const float* b2 = (const float*)d_in[6];
    float* out = (float*)d_out;

    int N = in_sizes[0] / DIM;
    int E = in_sizes[1];

    fuse_weights<<<257, 128>>>(W1, b1, W2, b2);
    zero_deg<<<(N + 255) / 256, 256>>>(N);
    histogram<<<(E + 255) / 256, 256>>>(dst, E);
    scan_offsets<<<1, 1024>>>(N);
    fill_csr<<<(E + 255) / 256, 256>>>(src, dst, E);

    long long gthreads = (long long)N * 32;
    gather_csr<<<(int)((gthreads + 255) / 256), 256>>>(h, N);

    fused_gemm<<<(N + BM - 1) / BM, 256>>>(h, out, N);
}

// round 3
// speedup vs baseline: 1.4278x; 1.4278x over previous
#include <cuda_runtime.h>
#include <cstdint>

// Problem constants: N=50000, E=600000, IN_DIM=128, HID=256, OUT=128
#define MAXN 50000
#define MAXE 600000
#define DIM 128
#define SCAN_BLK 512
#define MAX_SBLK 128   // >= ceil(MAXN/SCAN_BLK) = 98

// Scratch (device globals — no allocation allowed)
__device__ float g_msg[MAXN * DIM];   // neighbor means [N,128]
__device__ int   g_deg[MAXN];
__device__ int   g_off[MAXN];         // CSR row offsets (exclusive)
__device__ int   g_cur[MAXN];         // fill cursors
__device__ int   g_csr[MAXE];         // src index per CSR slot
__device__ int   g_bsum[MAX_SBLK];    // per-block degree sums
__device__ float g_W[256 * 128];      // fused W1@W2
__device__ float g_b[128];            // fused b1@W2 + b2

// ---------------------------------------------------------------------------
// Kernel 1: fuse the two linear layers (no inner activation => collapse)
// ---------------------------------------------------------------------------
__global__ void fuse_weights(const float* __restrict__ W1, const float* __restrict__ b1,
                             const float* __restrict__ W2, const float* __restrict__ b2) {
    int row = blockIdx.x;
    int j = threadIdx.x;            // 0..127
    if (row < 256) {
        float acc = 0.f;
        #pragma unroll 4
        for (int k = 0; k < 256; k++)
            acc += W1[row * 256 + k] * W2[k * 128 + j];
        g_W[row * 128 + j] = acc;
    } else {
        float acc = b2[j];
        #pragma unroll 4
        for (int k = 0; k < 256; k++)
            acc += b1[k] * W2[k * 128 + j];
        g_b[j] = acc;
    }
}

// ---------------------------------------------------------------------------
// Kernel 2: zero degree counters
// ---------------------------------------------------------------------------
__global__ void zero_deg(int n) {
    int i = blockIdx.x * blockDim.x + threadIdx.x;
    if (i < n) g_deg[i] = 0;
}

// ---------------------------------------------------------------------------
// Kernel 3: degree histogram (int atomics on 50K L2-resident counters)
// ---------------------------------------------------------------------------
__global__ void histogram(const int* __restrict__ dst, int E) {
    int e = blockIdx.x * blockDim.x + threadIdx.x;
    if (e < E) atomicAdd(&g_deg[dst[e]], 1);
}

// ---------------------------------------------------------------------------
// Kernels 4a/4b/4c: grid-wide exclusive prefix scan of degrees
// ---------------------------------------------------------------------------
__global__ __launch_bounds__(SCAN_BLK) void scan_reduce(int n) {
    __shared__ int sh[SCAN_BLK];
    int i = blockIdx.x * SCAN_BLK + threadIdx.x;
    int v = (i < n) ? g_deg[i] : 0;
    sh[threadIdx.x] = v;
    __syncthreads();
    for (int ofs = SCAN_BLK / 2; ofs > 0; ofs >>= 1) {
        if (threadIdx.x < ofs) sh[threadIdx.x] += sh[threadIdx.x + ofs];
        __syncthreads();
    }
    if (threadIdx.x == 0) g_bsum[blockIdx.x] = sh[0];
}

__global__ __launch_bounds__(MAX_SBLK) void scan_spine(int nblocks) {
    __shared__ int sh[MAX_SBLK];
    int t = threadIdx.x;
    sh[t] = (t < nblocks) ? g_bsum[t] : 0;
    __syncthreads();
    #pragma unroll
    for (int ofs = 1; ofs < MAX_SBLK; ofs <<= 1) {
        int v = (t >= ofs) ? sh[t - ofs] : 0;
        __syncthreads();
        sh[t] += v;
        __syncthreads();
    }
    // store exclusive block offset
    if (t < nblocks) g_bsum[t] = sh[t] - ((t < nblocks) ? ((t == 0) ? sh[0] : sh[t] - sh[t - 1]) : 0) - ((t == 0) ? 0 : 0), // (unused, replaced below)
    g_bsum[t] = (t == 0) ? 0 : sh[t - 1];
}

__global__ __launch_bounds__(SCAN_BLK) void scan_downsweep(int n) {
    __shared__ int sh[SCAN_BLK];
    int i = blockIdx.x * SCAN_BLK + threadIdx.x;
    int t = threadIdx.x;
    int v = (i < n) ? g_deg[i] : 0;
    sh[t] = v;
    __syncthreads();
    // Hillis-Steele inclusive scan
    #pragma unroll
    for (int ofs = 1; ofs < SCAN_BLK; ofs <<= 1) {
        int u = (t >= ofs) ? sh[t - ofs] : 0;
        __syncthreads();
        sh[t] += u;
        __syncthreads();
    }
    if (i < n) {
        int excl = sh[t] - v + g_bsum[blockIdx.x];
        g_off[i] = excl;
        g_cur[i] = excl;
    }
}

// ---------------------------------------------------------------------------
// Kernel 5: bucket-fill CSR (int atomics for slot assignment)
// ---------------------------------------------------------------------------
__global__ void fill_csr(const int* __restrict__ src, const int* __restrict__ dst, int E) {
    int e = blockIdx.x * blockDim.x + threadIdx.x;
    if (e >= E) return;
    int p = atomicAdd(&g_cur[dst[e]], 1);
    g_csr[p] = src[e];
}

// ---------------------------------------------------------------------------
// Kernel 6: gather + mean. One warp per node, lane l owns floats [4l,4l+4).
// ---------------------------------------------------------------------------
__global__ void gather_csr(const float* __restrict__ h, int n) {
    int warp = (blockIdx.x * blockDim.x + threadIdx.x) >> 5;
    int lane = threadIdx.x & 31;
    if (warp >= n) return;
    int beg = g_off[warp];
    int deg = g_deg[warp];
    float4 acc = make_float4(0.f, 0.f, 0.f, 0.f);

    for (int i = 0; i < deg; i += 32) {
        int idx = (i + lane < deg) ? g_csr[beg + i + lane] : 0;
        int m = min(32, deg - i);
        #pragma unroll 4
        for (int j = 0; j < m; j++) {
            int s = __shfl_sync(0xffffffff, idx, j);
            float4 v = reinterpret_cast<const float4*>(h)[(size_t)s * (DIM / 4) + lane];
            acc.x += v.x; acc.y += v.y; acc.z += v.z; acc.w += v.w;
        }
    }
    float inv = 1.0f / fmaxf((float)deg, 1.0f);
    acc.x *= inv; acc.y *= inv; acc.z *= inv; acc.w *= inv;
    reinterpret_cast<float4*>(g_msg)[(size_t)warp * (DIM / 4) + lane] = acc;
}

// ---------------------------------------------------------------------------
// Kernel 7: fused GEMM + bias + relu.
//   out[n,:] = relu( [h[n,:], msg[n,:]] @ W + b )   (M=N, K=256, N=128)
// ---------------------------------------------------------------------------
#define BM 128
#define BN 128
#define BK 16
#define TM 8
#define TN 8

__global__ __launch_bounds__(256) void fused_gemm(const float* __restrict__ h,
                                                  float* __restrict__ out, int M) {
    __shared__ float As[BK][BM];   // transposed: As[k][m]
    __shared__ float Bs[BK][BN];

    int tid = threadIdx.x;
    int tx = tid & 15;     // N direction (16)
    int ty = tid >> 4;     // M direction (16)
    int row0 = blockIdx.x * BM;

    unsigned long long acc[TM][TN / 2];
    #pragma unroll
    for (int m = 0; m < TM; m++)
        #pragma unroll
        for (int j = 0; j < TN / 2; j++) acc[m][j] = 0ULL;

    for (int k0 = 0; k0 < 256; k0 += BK) {
        const float* Abase = (k0 < 128) ? (h + k0) : (g_msg + (k0 - 128));
        #pragma unroll
        for (int l = 0; l < 2; l++) {
            int idx = tid + l * 256;
            int r = idx >> 2;
            int c = (idx & 3) * 4;
            float4 v = make_float4(0.f, 0.f, 0.f, 0.f);
            int gr = row0 + r;
            if (gr < M)
                v = *reinterpret_cast<const float4*>(Abase + (size_t)gr * DIM + c);
            As[c + 0][r] = v.x; As[c + 1][r] = v.y;
            As[c + 2][r] = v.z; As[c + 3][r] = v.w;
        }
        #pragma unroll
        for (int l = 0; l < 2; l++) {
            int idx = tid + l * 256;
            int r = idx >> 5;
            int c = (idx & 31) * 4;
            *reinterpret_cast<float4*>(&Bs[r][c]) =
                *reinterpret_cast<const float4*>(g_W + (size_t)(k0 + r) * 128 + c);
        }
        __syncthreads();

        #pragma unroll
        for (int kk = 0; kk < BK; kk++) {
            float a[TM];
            #pragma unroll
            for (int m = 0; m < TM; m += 4) {
                float4 t = *reinterpret_cast<const float4*>(&As[kk][ty * TM + m]);
                a[m] = t.x; a[m + 1] = t.y; a[m + 2] = t.z; a[m + 3] = t.w;
            }
            unsigned long long b2v[4];
            const unsigned long long* bp =
                reinterpret_cast<const unsigned long long*>(&Bs[kk][tx * TN]);
            b2v[0] = bp[0]; b2v[1] = bp[1]; b2v[2] = bp[2]; b2v[3] = bp[3];
            #pragma unroll
            for (int m = 0; m < TM; m++) {
                unsigned long long aa;
                asm("mov.b64 %0, {%1, %1};" : "=l"(aa) : "f"(a[m]));
                #pragma unroll
                for (int j = 0; j < 4; j++)
                    asm("fma.rn.f32x2 %0, %1, %2, %0;"
                        : "+l"(acc[m][j]) : "l"(aa), "l"(b2v[j]));
            }
        }
        __syncthreads();
    }

    float bias[TN];
    #pragma unroll
    for (int j = 0; j < TN; j++) bias[j] = g_b[tx * TN + j];

    #pragma unroll
    for (int m = 0; m < TM; m++) {
        int gr = row0 + ty * TM + m;
        if (gr >= M) continue;
        float res[TN];
        #pragma unroll
        for (int j = 0; j < 4; j++) {
            float lo, hi;
            asm("mov.b64 {%0, %1}, %2;" : "=f"(lo), "=f"(hi) : "l"(acc[m][j]));
            res[2 * j] = lo; res[2 * j + 1] = hi;
        }
        float4 o0, o1;
        o0.x = fmaxf(res[0] + bias[0], 0.f);
        o0.y = fmaxf(res[1] + bias[1], 0.f);
        o0.z = fmaxf(res[2] + bias[2], 0.f);
        o0.w = fmaxf(res[3] + bias[3], 0.f);
        o1.x = fmaxf(res[4] + bias[4], 0.f);
        o1.y = fmaxf(res[5] + bias[5], 0.f);
        o1.z = fmaxf(res[6] + bias[6], 0.f);
        o1.w = fmaxf(res[7] + bias[7], 0.f);
        float* op = out + (size_t)gr * DIM + tx * TN;
        *reinterpret_cast<float4*>(op) = o0;
        *reinterpret_cast<float4*>(op + 4) = o1;
    }
}

// ---------------------------------------------------------------------------
extern "C" void kernel_launch(void* const* d_in, const int* in_sizes, int n_in,
                              void* d_out, int out_size) {
    const float* h  = (const float*)d_in[0];
    const int* src  = (const int*)d_in[1];
    const int* dst  = (const int*)d_in[2];
    const float* W1 = (const float*)d_in[3];
    const float* b1 = (const float*)d_in[4];
    const float* W2 = (const float*)d_in[5];
    const float* b2 = (const float*)d_in[6];
    float* out = (float*)d_out;

    int N = in_sizes[0] / DIM;
    int E = in_sizes[1];
    int nblocks = (N + SCAN_BLK - 1) / SCAN_BLK;   // 98 for N=50000

    fuse_weights<<<257, 128>>>(W1, b1, W2, b2);
    zero_deg<<<(N + 255) / 256, 256>>>(N);
    histogram<<<(E + 255) / 256, 256>>>(dst, E);

    scan_reduce<<<nblocks, SCAN_BLK>>>(N);
    scan_spine<<<1, MAX_SBLK>>>(nblocks);
    scan_downsweep<<<nblocks, SCAN_BLK>>>(N);

    fill_csr<<<(E + 255) / 256, 256>>>(src, dst, E);

    long long gthreads = (long long)N * 32;
    gather_csr<<<(int)((gthreads + 255) / 256), 256>>>(h, N);

    fused_gemm<<<(N + BM - 1) / BM, 256>>>(h, out, N);
}

// round 5
// speedup vs baseline: 1.8968x; 1.3284x over previous
#include <cuda_runtime.h>
#include <cuda_bf16.h>
#include <cstdint>

// Problem constants: N=50000, E=600000, IN_DIM=128, HID=256, OUT=128
#define MAXN 50000
#define MAXE 600000
#define DIM 128
#define SCAN_BLK 512
#define MAX_SBLK 128

// Scratch (device globals — no allocation allowed)
__device__ float g_msg[MAXN * DIM];
__device__ int   g_deg[MAXN];
__device__ int   g_off[MAXN];
__device__ int   g_cur[MAXN];
__device__ int   g_csr[MAXE];
__device__ int   g_bsum[MAX_SBLK];
__device__ __nv_bfloat16 g_Wh[256 * 128];   // hi part of fused W1@W2
__device__ __nv_bfloat16 g_Wl[256 * 128];   // lo part
__device__ float g_b[128];                  // fused bias

static __device__ __forceinline__ uint32_t s2u(const void* p) {
    return (uint32_t)__cvta_generic_to_shared(p);
}

// ---------------------------------------------------------------------------
// Kernel 1: fuse layers: W = W1@W2 (split to bf16 hi/lo), b = b1@W2 + b2
// ---------------------------------------------------------------------------
__global__ void fuse_weights(const float* __restrict__ W1, const float* __restrict__ b1,
                             const float* __restrict__ W2, const float* __restrict__ b2) {
    int row = blockIdx.x;
    int j = threadIdx.x;            // 0..127
    if (row < 256) {
        float acc = 0.f;
        #pragma unroll 4
        for (int k = 0; k < 256; k++)
            acc += W1[row * 256 + k] * W2[k * 128 + j];
        __nv_bfloat16 hi = __float2bfloat16(acc);
        __nv_bfloat16 lo = __float2bfloat16(acc - __bfloat162float(hi));
        g_Wh[row * 128 + j] = hi;
        g_Wl[row * 128 + j] = lo;
    } else {
        float acc = b2[j];
        #pragma unroll 4
        for (int k = 0; k < 256; k++)
            acc += b1[k] * W2[k * 128 + j];
        g_b[j] = acc;
    }
}

// ---------------------------------------------------------------------------
// Kernel 2: zero degree counters
// ---------------------------------------------------------------------------
__global__ void zero_deg(int n) {
    int i = blockIdx.x * blockDim.x + threadIdx.x;
    if (i < n) g_deg[i] = 0;
}

// ---------------------------------------------------------------------------
// Kernel 3: degree histogram
// ---------------------------------------------------------------------------
__global__ void histogram(const int* __restrict__ dst, int E) {
    int e = blockIdx.x * blockDim.x + threadIdx.x;
    if (e < E) atomicAdd(&g_deg[dst[e]], 1);
}

// ---------------------------------------------------------------------------
// Kernels 4a/4b/4c: grid-wide exclusive prefix scan of degrees
// ---------------------------------------------------------------------------
__global__ __launch_bounds__(SCAN_BLK) void scan_reduce(int n) {
    __shared__ int sh[SCAN_BLK];
    int i = blockIdx.x * SCAN_BLK + threadIdx.x;
    sh[threadIdx.x] = (i < n) ? g_deg[i] : 0;
    __syncthreads();
    for (int ofs = SCAN_BLK / 2; ofs > 0; ofs >>= 1) {
        if (threadIdx.x < ofs) sh[threadIdx.x] += sh[threadIdx.x + ofs];
        __syncthreads();
    }
    if (threadIdx.x == 0) g_bsum[blockIdx.x] = sh[0];
}

__global__ __launch_bounds__(MAX_SBLK) void scan_spine(int nblocks) {
    __shared__ int sh[MAX_SBLK];
    int t = threadIdx.x;
    sh[t] = (t < nblocks) ? g_bsum[t] : 0;
    __syncthreads();
    #pragma unroll
    for (int ofs = 1; ofs < MAX_SBLK; ofs <<= 1) {
        int v = (t >= ofs) ? sh[t - ofs] : 0;
        __syncthreads();
        sh[t] += v;
        __syncthreads();
    }
    g_bsum[t] = (t == 0) ? 0 : sh[t - 1];   // exclusive
}

__global__ __launch_bounds__(SCAN_BLK) void scan_downsweep(int n) {
    __shared__ int sh[SCAN_BLK];
    int i = blockIdx.x * SCAN_BLK + threadIdx.x;
    int t = threadIdx.x;
    int v = (i < n) ? g_deg[i] : 0;
    sh[t] = v;
    __syncthreads();
    #pragma unroll
    for (int ofs = 1; ofs < SCAN_BLK; ofs <<= 1) {
        int u = (t >= ofs) ? sh[t - ofs] : 0;
        __syncthreads();
        sh[t] += u;
        __syncthreads();
    }
    if (i < n) {
        int excl = sh[t] - v + g_bsum[blockIdx.x];
        g_off[i] = excl;
        g_cur[i] = excl;
    }
}

// ---------------------------------------------------------------------------
// Kernel 5: bucket-fill CSR
// ---------------------------------------------------------------------------
__global__ void fill_csr(const int* __restrict__ src, const int* __restrict__ dst, int E) {
    int e = blockIdx.x * blockDim.x + threadIdx.x;
    if (e >= E) return;
    int p = atomicAdd(&g_cur[dst[e]], 1);
    g_csr[p] = src[e];
}

// ---------------------------------------------------------------------------
// Kernel 6: gather + mean. One warp per node.
// ---------------------------------------------------------------------------
__global__ void gather_csr(const float* __restrict__ h, int n) {
    int warp = (blockIdx.x * blockDim.x + threadIdx.x) >> 5;
    int lane = threadIdx.x & 31;
    if (warp >= n) return;
    int beg = g_off[warp];
    int deg = g_deg[warp];
    float4 acc = make_float4(0.f, 0.f, 0.f, 0.f);

    for (int i = 0; i < deg; i += 32) {
        int idx = (i + lane < deg) ? g_csr[beg + i + lane] : 0;
        int m = min(32, deg - i);
        #pragma unroll 4
        for (int j = 0; j < m; j++) {
            int s = __shfl_sync(0xffffffff, idx, j);
            float4 v = reinterpret_cast<const float4*>(h)[(size_t)s * (DIM / 4) + lane];
            acc.x += v.x; acc.y += v.y; acc.z += v.z; acc.w += v.w;
        }
    }
    float inv = 1.0f / fmaxf((float)deg, 1.0f);
    acc.x *= inv; acc.y *= inv; acc.z *= inv; acc.w *= inv;
    reinterpret_cast<float4*>(g_msg)[(size_t)warp * (DIM / 4) + lane] = acc;
}

// ---------------------------------------------------------------------------
// Kernel 7: tensor-core GEMM + bias + relu (bf16 3-way split, mma.sync)
//   out[n,:] = relu( [h | msg] @ (Whi+Wlo) + b ),  M=N nodes, K=256, N=128
// Block: 256 thr (8 warps), tile 128x128, warp tile 64x32, BK=32.
// Smem strides are multiples of 8 elements (16B) for ldmatrix alignment:
//   LDA=40 (80B rows, bank phase 20r mod 32: all 8 distinct)
//   LDB=136 (272B rows, bank phase 4r mod 32: all 8 distinct)
// ---------------------------------------------------------------------------
#define GBM 128
#define GBK 32
#define LDA 40
#define LDB 136

#define MMA_B16(d, a, b)                                                        \
    asm volatile("mma.sync.aligned.m16n8k16.row.col.f32.bf16.bf16.f32 "         \
                 "{%0,%1,%2,%3}, {%4,%5,%6,%7}, {%8,%9}, {%0,%1,%2,%3};"        \
                 : "+f"(d[0]), "+f"(d[1]), "+f"(d[2]), "+f"(d[3])               \
                 : "r"(a[0]), "r"(a[1]), "r"(a[2]), "r"(a[3]),                  \
                   "r"(b[0]), "r"(b[1]))

__global__ __launch_bounds__(256, 2) void fused_gemm_mma(const float* __restrict__ h,
                                                         float* __restrict__ out, int M) {
    __shared__ __nv_bfloat16 Ah[GBM * LDA], Al[GBM * LDA];
    __shared__ __nv_bfloat16 Bh[GBK * LDB], Bl[GBK * LDB];

    int tid = threadIdx.x;
    int lane = tid & 31;
    int warp = tid >> 5;
    int wm = (warp >> 2) * 64;   // 0 / 64
    int wn = (warp & 3) * 32;    // 0..96
    int row0 = blockIdx.x * GBM;

    float acc[4][4][4];
    #pragma unroll
    for (int mt = 0; mt < 4; mt++)
        #pragma unroll
        for (int nt = 0; nt < 4; nt++)
            #pragma unroll
            for (int r = 0; r < 4; r++) acc[mt][nt][r] = 0.f;

    for (int kc = 0; kc < 8; kc++) {
        int k0 = kc * GBK;
        const float* Abase = (k0 < 128) ? (h + k0) : (g_msg + (k0 - 128));

        // --- load A tile (128x32 fp32), split to bf16 hi/lo in smem ---
        #pragma unroll
        for (int l = 0; l < 4; l++) {
            int idx = tid + l * 256;
            int r = idx >> 3;            // row in tile
            int c = (idx & 7) * 4;       // k offset
            float4 v = make_float4(0.f, 0.f, 0.f, 0.f);
            int gr = row0 + r;
            if (gr < M) v = *reinterpret_cast<const float4*>(Abase + (size_t)gr * DIM + c);
            float f[4] = {v.x, v.y, v.z, v.w};
            __nv_bfloat16 h0 = __float2bfloat16(f[0]);
            __nv_bfloat16 h1 = __float2bfloat16(f[1]);
            __nv_bfloat16 h2 = __float2bfloat16(f[2]);
            __nv_bfloat16 h3 = __float2bfloat16(f[3]);
            __nv_bfloat162 hp0 = __nv_bfloat162(h0, h1);
            __nv_bfloat162 hp1 = __nv_bfloat162(h2, h3);
            __nv_bfloat162 lp0 = __nv_bfloat162(__float2bfloat16(f[0] - __bfloat162float(h0)),
                                                __float2bfloat16(f[1] - __bfloat162float(h1)));
            __nv_bfloat162 lp1 = __nv_bfloat162(__float2bfloat16(f[2] - __bfloat162float(h2)),
                                                __float2bfloat16(f[3] - __bfloat162float(h3)));
            *reinterpret_cast<__nv_bfloat162*>(&Ah[r * LDA + c])     = hp0;
            *reinterpret_cast<__nv_bfloat162*>(&Ah[r * LDA + c + 2]) = hp1;
            *reinterpret_cast<__nv_bfloat162*>(&Al[r * LDA + c])     = lp0;
            *reinterpret_cast<__nv_bfloat162*>(&Al[r * LDA + c + 2]) = lp1;
        }
        // --- load B tile (32x128 bf16 hi + lo) ---
        #pragma unroll
        for (int l = 0; l < 4; l++) {
            int idx = tid + l * 256;
            int r = idx >> 5;            // k row
            int c = (idx & 31) * 4;      // n offset
            uint2 vh = *reinterpret_cast<const uint2*>(&g_Wh[(size_t)(k0 + r) * 128 + c]);
            uint2 vl = *reinterpret_cast<const uint2*>(&g_Wl[(size_t)(k0 + r) * 128 + c]);
            *reinterpret_cast<uint2*>(&Bh[r * LDB + c]) = vh;
            *reinterpret_cast<uint2*>(&Bl[r * LDB + c]) = vl;
        }
        __syncthreads();

        #pragma unroll
        for (int ks = 0; ks < 2; ks++) {
            uint32_t ah[4][4], al[4][4], bh[4][2], bl[4][2];
            #pragma unroll
            for (int mt = 0; mt < 4; mt++) {
                int r = wm + mt * 16 + (lane & 15);
                int eo = r * LDA + ks * 16 + ((lane >> 4) * 8);
                uint32_t ad = s2u(&Ah[eo]);
                asm volatile("ldmatrix.sync.aligned.m8n8.x4.shared.b16 {%0,%1,%2,%3}, [%4];"
                             : "=r"(ah[mt][0]), "=r"(ah[mt][1]), "=r"(ah[mt][2]), "=r"(ah[mt][3])
                             : "r"(ad));
                uint32_t ad2 = s2u(&Al[eo]);
                asm volatile("ldmatrix.sync.aligned.m8n8.x4.shared.b16 {%0,%1,%2,%3}, [%4];"
                             : "=r"(al[mt][0]), "=r"(al[mt][1]), "=r"(al[mt][2]), "=r"(al[mt][3])
                             : "r"(ad2));
            }
            #pragma unroll
            for (int nt = 0; nt < 4; nt++) {
                int kr = ks * 16 + (lane & 15);
                int eo = kr * LDB + wn + nt * 8;
                uint32_t bd = s2u(&Bh[eo]);
                asm volatile("ldmatrix.sync.aligned.m8n8.x2.trans.shared.b16 {%0,%1}, [%2];"
                             : "=r"(bh[nt][0]), "=r"(bh[nt][1]) : "r"(bd));
                uint32_t bd2 = s2u(&Bl[eo]);
                asm volatile("ldmatrix.sync.aligned.m8n8.x2.trans.shared.b16 {%0,%1}, [%2];"
                             : "=r"(bl[nt][0]), "=r"(bl[nt][1]) : "r"(bd2));
            }
            #pragma unroll
            for (int mt = 0; mt < 4; mt++)
                #pragma unroll
                for (int nt = 0; nt < 4; nt++) {
                    MMA_B16(acc[mt][nt], ah[mt], bh[nt]);   // hi*hi
                    MMA_B16(acc[mt][nt], ah[mt], bl[nt]);   // hi*lo
                    MMA_B16(acc[mt][nt], al[mt], bh[nt]);   // lo*hi
                }
        }
        __syncthreads();
    }

    // --- epilogue: bias + relu, float2 stores ---
    #pragma unroll
    for (int mt = 0; mt < 4; mt++) {
        int r0 = row0 + wm + mt * 16 + (lane >> 2);
        #pragma unroll
        for (int nt = 0; nt < 4; nt++) {
            int col = wn + nt * 8 + (lane & 3) * 2;
            float b0 = g_b[col], b1 = g_b[col + 1];
            if (r0 < M) {
                float2 o;
                o.x = fmaxf(acc[mt][nt][0] + b0, 0.f);
                o.y = fmaxf(acc[mt][nt][1] + b1, 0.f);
                *reinterpret_cast<float2*>(&out[(size_t)r0 * DIM + col]) = o;
            }
            int r1 = r0 + 8;
            if (r1 < M) {
                float2 o;
                o.x = fmaxf(acc[mt][nt][2] + b0, 0.f);
                o.y = fmaxf(acc[mt][nt][3] + b1, 0.f);
                *reinterpret_cast<float2*>(&out[(size_t)r1 * DIM + col]) = o;
            }
        }
    }
}

// ---------------------------------------------------------------------------
extern "C" void kernel_launch(void* const* d_in, const int* in_sizes, int n_in,
                              void* d_out, int out_size) {
    const float* h  = (const float*)d_in[0];
    const int* src  = (const int*)d_in[1];
    const int* dst  = (const int*)d_in[2];
    const float* W1 = (const float*)d_in[3];
    const float* b1 = (const float*)d_in[4];
    const float* W2 = (const float*)d_in[5];
    const float* b2 = (const float*)d_in[6];
    float* out = (float*)d_out;

    int N = in_sizes[0] / DIM;
    int E = in_sizes[1];
    int nblocks = (N + SCAN_BLK - 1) / SCAN_BLK;

    fuse_weights<<<257, 128>>>(W1, b1, W2, b2);
    zero_deg<<<(N + 255) / 256, 256>>>(N);
    histogram<<<(E + 255) / 256, 256>>>(dst, E);

    scan_reduce<<<nblocks, SCAN_BLK>>>(N);
    scan_spine<<<1, MAX_SBLK>>>(nblocks);
    scan_downsweep<<<nblocks, SCAN_BLK>>>(N);

    fill_csr<<<(E + 255) / 256, 256>>>(src, dst, E);

    long long gthreads = (long long)N * 32;
    gather_csr<<<(int)((gthreads + 255) / 256), 256>>>(h, N);

    fused_gemm_mma<<<(N + GBM - 1) / GBM, 256>>>(h, out, N);
}

// round 6
// speedup vs baseline: 1.9577x; 1.0321x over previous
#include <cuda_runtime.h>
#include <cuda_bf16.h>
#include <cstdint>

// Problem constants: N=50000, E=600000, IN_DIM=128, HID=256, OUT=128
#define MAXN 50000
#define MAXE 600000
#define DIM 128
#define SCAN_BLK 512
#define MAX_SBLK 128

// Scratch (device globals — no allocation allowed)
__device__ float g_msg[MAXN * DIM];
__device__ int   g_deg[MAXN];
__device__ int   g_off[MAXN];
__device__ int   g_rank[MAXE];              // per-edge rank within dst bucket
__device__ int   g_csr[MAXE];
__device__ int   g_agg[MAX_SBLK];           // scan block aggregates
__device__ int   g_flagS[MAX_SBLK];         // scan publish flags
__device__ __nv_bfloat16 g_Wh[256 * 128];   // hi part of fused W1@W2
__device__ __nv_bfloat16 g_Wl[256 * 128];   // lo part
__device__ float g_b[128];                  // fused bias

static __device__ __forceinline__ uint32_t s2u(const void* p) {
    return (uint32_t)__cvta_generic_to_shared(p);
}

// ---------------------------------------------------------------------------
// Kernel 1: fuse layers (W=W1@W2 split to bf16 hi/lo, b=b1@W2+b2)
//           + zero g_deg (blocks 257..) + zero scan flags (block 0)
// ---------------------------------------------------------------------------
__global__ void fuse_weights(const float* __restrict__ W1, const float* __restrict__ b1,
                             const float* __restrict__ W2, const float* __restrict__ b2,
                             int n) {
    int row = blockIdx.x;
    int j = threadIdx.x;            // 0..127
    if (row == 0 && j < MAX_SBLK) g_flagS[j] = 0;
    if (row < 256) {
        float acc = 0.f;
        #pragma unroll 4
        for (int k = 0; k < 256; k++)
            acc += W1[row * 256 + k] * W2[k * 128 + j];
        __nv_bfloat16 hi = __float2bfloat16(acc);
        __nv_bfloat16 lo = __float2bfloat16(acc - __bfloat162float(hi));
        g_Wh[row * 128 + j] = hi;
        g_Wl[row * 128 + j] = lo;
    } else if (row == 256) {
        float acc = b2[j];
        #pragma unroll 4
        for (int k = 0; k < 256; k++)
            acc += b1[k] * W2[k * 128 + j];
        g_b[j] = acc;
    } else {
        int i = (row - 257) * 128 + j;
        if (i < n) g_deg[i] = 0;
    }
}

// ---------------------------------------------------------------------------
// Kernel 2: degree histogram; atomic return value = edge rank in dst bucket
// ---------------------------------------------------------------------------
__global__ void histogram(const int* __restrict__ dst, int E) {
    int e = blockIdx.x * blockDim.x + threadIdx.x;
    if (e < E) g_rank[e] = atomicAdd(&g_deg[dst[e]], 1);
}

// ---------------------------------------------------------------------------
// Kernel 3: one-launch exclusive scan (decoupled lookback; 98 blocks all
// co-resident on 148 SMs so cross-block spin is safe)
// ---------------------------------------------------------------------------
__global__ __launch_bounds__(SCAN_BLK) void scan_onepass(int n) {
    __shared__ int sh[SCAN_BLK];
    __shared__ int red[SCAN_BLK];
    int b = blockIdx.x, t = threadIdx.x;
    int i = b * SCAN_BLK + t;
    int v = (i < n) ? g_deg[i] : 0;
    sh[t] = v;
    __syncthreads();
    #pragma unroll
    for (int o = 1; o < SCAN_BLK; o <<= 1) {
        int u = (t >= o) ? sh[t - o] : 0;
        __syncthreads();
        sh[t] += u;
        __syncthreads();
    }
    if (t == 0) {
        g_agg[b] = sh[SCAN_BLK - 1];
        __threadfence();
        atomicExch(&g_flagS[b], 1);
    }
    // lookback: thread t (< b) fetches predecessor t's aggregate
    int part = 0;
    if (t < b) {   // b <= 97 < 512, single pass
        while (atomicAdd(&g_flagS[t], 0) == 0) {}
        part = g_agg[t];
    }
    red[t] = part;
    __syncthreads();
    #pragma unroll
    for (int o = SCAN_BLK / 2; o > 0; o >>= 1) {
        if (t < o) red[t] += red[t + o];
        __syncthreads();
    }
    if (i < n) g_off[i] = red[0] + sh[t] - v;   // exclusive
}

// ---------------------------------------------------------------------------
// Kernel 4: atomic-free CSR fill using precomputed ranks
// ---------------------------------------------------------------------------
__global__ void fill_csr(const int* __restrict__ src, const int* __restrict__ dst, int E) {
    int e = blockIdx.x * blockDim.x + threadIdx.x;
    if (e >= E) return;
    g_csr[g_off[dst[e]] + g_rank[e]] = src[e];
}

// ---------------------------------------------------------------------------
// Kernel 5: gather + mean. One warp per node.
// ---------------------------------------------------------------------------
__global__ void gather_csr(const float* __restrict__ h, int n) {
    int warp = (blockIdx.x * blockDim.x + threadIdx.x) >> 5;
    int lane = threadIdx.x & 31;
    if (warp >= n) return;
    int beg = g_off[warp];
    int deg = g_deg[warp];
    float4 acc = make_float4(0.f, 0.f, 0.f, 0.f);

    for (int i = 0; i < deg; i += 32) {
        int idx = (i + lane < deg) ? g_csr[beg + i + lane] : 0;
        int m = min(32, deg - i);
        #pragma unroll 4
        for (int j = 0; j < m; j++) {
            int s = __shfl_sync(0xffffffff, idx, j);
            float4 v = reinterpret_cast<const float4*>(h)[(size_t)s * (DIM / 4) + lane];
            acc.x += v.x; acc.y += v.y; acc.z += v.z; acc.w += v.w;
        }
    }
    float inv = 1.0f / fmaxf((float)deg, 1.0f);
    acc.x *= inv; acc.y *= inv; acc.z *= inv; acc.w *= inv;
    reinterpret_cast<float4*>(g_msg)[(size_t)warp * (DIM / 4) + lane] = acc;
}

// ---------------------------------------------------------------------------
// Kernel 6: tensor-core GEMM + bias + relu (bf16 3-way split, mma.sync)
// ---------------------------------------------------------------------------
#define GBM 128
#define GBK 32
#define LDA 40
#define LDB 136

#define MMA_B16(d, a, b)                                                        \
    asm volatile("mma.sync.aligned.m16n8k16.row.col.f32.bf16.bf16.f32 "         \
                 "{%0,%1,%2,%3}, {%4,%5,%6,%7}, {%8,%9}, {%0,%1,%2,%3};"        \
                 : "+f"(d[0]), "+f"(d[1]), "+f"(d[2]), "+f"(d[3])               \
                 : "r"(a[0]), "r"(a[1]), "r"(a[2]), "r"(a[3]),                  \
                   "r"(b[0]), "r"(b[1]))

__global__ __launch_bounds__(256, 2) void fused_gemm_mma(const float* __restrict__ h,
                                                         float* __restrict__ out, int M) {
    __shared__ __nv_bfloat16 Ah[GBM * LDA], Al[GBM * LDA];
    __shared__ __nv_bfloat16 Bh[GBK * LDB], Bl[GBK * LDB];

    int tid = threadIdx.x;
    int lane = tid & 31;
    int warp = tid >> 5;
    int wm = (warp >> 2) * 64;
    int wn = (warp & 3) * 32;
    int row0 = blockIdx.x * GBM;

    float acc[4][4][4];
    #pragma unroll
    for (int mt = 0; mt < 4; mt++)
        #pragma unroll
        for (int nt = 0; nt < 4; nt++)
            #pragma unroll
            for (int r = 0; r < 4; r++) acc[mt][nt][r] = 0.f;

    for (int kc = 0; kc < 8; kc++) {
        int k0 = kc * GBK;
        const float* Abase = (k0 < 128) ? (h + k0) : (g_msg + (k0 - 128));

        #pragma unroll
        for (int l = 0; l < 4; l++) {
            int idx = tid + l * 256;
            int r = idx >> 3;
            int c = (idx & 7) * 4;
            float4 v = make_float4(0.f, 0.f, 0.f, 0.f);
            int gr = row0 + r;
            if (gr < M) v = *reinterpret_cast<const float4*>(Abase + (size_t)gr * DIM + c);
            float f[4] = {v.x, v.y, v.z, v.w};
            __nv_bfloat16 h0 = __float2bfloat16(f[0]);
            __nv_bfloat16 h1 = __float2bfloat16(f[1]);
            __nv_bfloat16 h2 = __float2bfloat16(f[2]);
            __nv_bfloat16 h3 = __float2bfloat16(f[3]);
            __nv_bfloat162 hp0 = __nv_bfloat162(h0, h1);
            __nv_bfloat162 hp1 = __nv_bfloat162(h2, h3);
            __nv_bfloat162 lp0 = __nv_bfloat162(__float2bfloat16(f[0] - __bfloat162float(h0)),
                                                __float2bfloat16(f[1] - __bfloat162float(h1)));
            __nv_bfloat162 lp1 = __nv_bfloat162(__float2bfloat16(f[2] - __bfloat162float(h2)),
                                                __float2bfloat16(f[3] - __bfloat162float(h3)));
            *reinterpret_cast<__nv_bfloat162*>(&Ah[r * LDA + c])     = hp0;
            *reinterpret_cast<__nv_bfloat162*>(&Ah[r * LDA + c + 2]) = hp1;
            *reinterpret_cast<__nv_bfloat162*>(&Al[r * LDA + c])     = lp0;
            *reinterpret_cast<__nv_bfloat162*>(&Al[r * LDA + c + 2]) = lp1;
        }
        #pragma unroll
        for (int l = 0; l < 4; l++) {
            int idx = tid + l * 256;
            int r = idx >> 5;
            int c = (idx & 31) * 4;
            uint2 vh = *reinterpret_cast<const uint2*>(&g_Wh[(size_t)(k0 + r) * 128 + c]);
            uint2 vl = *reinterpret_cast<const uint2*>(&g_Wl[(size_t)(k0 + r) * 128 + c]);
            *reinterpret_cast<uint2*>(&Bh[r * LDB + c]) = vh;
            *reinterpret_cast<uint2*>(&Bl[r * LDB + c]) = vl;
        }
        __syncthreads();

        #pragma unroll
        for (int ks = 0; ks < 2; ks++) {
            uint32_t ah[4][4], al[4][4], bh[4][2], bl[4][2];
            #pragma unroll
            for (int mt = 0; mt < 4; mt++) {
                int r = wm + mt * 16 + (lane & 15);
                int eo = r * LDA + ks * 16 + ((lane >> 4) * 8);
                uint32_t ad = s2u(&Ah[eo]);
                asm volatile("ldmatrix.sync.aligned.m8n8.x4.shared.b16 {%0,%1,%2,%3}, [%4];"
                             : "=r"(ah[mt][0]), "=r"(ah[mt][1]), "=r"(ah[mt][2]), "=r"(ah[mt][3])
                             : "r"(ad));
                uint32_t ad2 = s2u(&Al[eo]);
                asm volatile("ldmatrix.sync.aligned.m8n8.x4.shared.b16 {%0,%1,%2,%3}, [%4];"
                             : "=r"(al[mt][0]), "=r"(al[mt][1]), "=r"(al[mt][2]), "=r"(al[mt][3])
                             : "r"(ad2));
            }
            #pragma unroll
            for (int nt = 0; nt < 4; nt++) {
                int kr = ks * 16 + (lane & 15);
                int eo = kr * LDB + wn + nt * 8;
                uint32_t bd = s2u(&Bh[eo]);
                asm volatile("ldmatrix.sync.aligned.m8n8.x2.trans.shared.b16 {%0,%1}, [%2];"
                             : "=r"(bh[nt][0]), "=r"(bh[nt][1]) : "r"(bd));
                uint32_t bd2 = s2u(&Bl[eo]);
                asm volatile("ldmatrix.sync.aligned.m8n8.x2.trans.shared.b16 {%0,%1}, [%2];"
                             : "=r"(bl[nt][0]), "=r"(bl[nt][1]) : "r"(bd2));
            }
            #pragma unroll
            for (int mt = 0; mt < 4; mt++)
                #pragma unroll
                for (int nt = 0; nt < 4; nt++) {
                    MMA_B16(acc[mt][nt], ah[mt], bh[nt]);
                    MMA_B16(acc[mt][nt], ah[mt], bl[nt]);
                    MMA_B16(acc[mt][nt], al[mt], bh[nt]);
                }
        }
        __syncthreads();
    }

    #pragma unroll
    for (int mt = 0; mt < 4; mt++) {
        int r0 = row0 + wm + mt * 16 + (lane >> 2);
        #pragma unroll
        for (int nt = 0; nt < 4; nt++) {
            int col = wn + nt * 8 + (lane & 3) * 2;
            float b0 = g_b[col], b1 = g_b[col + 1];
            if (r0 < M) {
                float2 o;
                o.x = fmaxf(acc[mt][nt][0] + b0, 0.f);
                o.y = fmaxf(acc[mt][nt][1] + b1, 0.f);
                *reinterpret_cast<float2*>(&out[(size_t)r0 * DIM + col]) = o;
            }
            int r1 = r0 + 8;
            if (r1 < M) {
                float2 o;
                o.x = fmaxf(acc[mt][nt][2] + b0, 0.f);
                o.y = fmaxf(acc[mt][nt][3] + b1, 0.f);
                *reinterpret_cast<float2*>(&out[(size_t)r1 * DIM + col]) = o;
            }
        }
    }
}

// ---------------------------------------------------------------------------
extern "C" void kernel_launch(void* const* d_in, const int* in_sizes, int n_in,
                              void* d_out, int out_size) {
    const float* h  = (const float*)d_in[0];
    const int* src  = (const int*)d_in[1];
    const int* dst  = (const int*)d_in[2];
    const float* W1 = (const float*)d_in[3];
    const float* b1 = (const float*)d_in[4];
    const float* W2 = (const float*)d_in[5];
    const float* b2 = (const float*)d_in[6];
    float* out = (float*)d_out;

    int N = in_sizes[0] / DIM;
    int E = in_sizes[1];
    int zblocks = (N + 127) / 128;
    int sblocks = (N + SCAN_BLK - 1) / SCAN_BLK;   // 98

    fuse_weights<<<257 + zblocks, 128>>>(W1, b1, W2, b2, N);
    histogram<<<(E + 255) / 256, 256>>>(dst, E);
    scan_onepass<<<sblocks, SCAN_BLK>>>(N);
    fill_csr<<<(E + 255) / 256, 256>>>(src, dst, E);

    long long gthreads = (long long)N * 32;
    gather_csr<<<(int)((gthreads + 255) / 256), 256>>>(h, N);

    fused_gemm_mma<<<(N + GBM - 1) / GBM, 256>>>(h, out, N);
}